// round 15
// baseline (speedup 1.0000x reference)
#include <cuda_runtime.h>
#include <cuda_bf16.h>
#include <cstdint>
#include <cstddef>

#define D 128
#define NMAX 100096   // multiple of 128
#define EMAX 800000
#define PITCH 68      // u32 per smem row (136 bf16): ldmatrix conflict-free

// ---------------- scratch (device globals; no allocation allowed) ----------------
__device__ __align__(128) float    g_degO[NMAX];
__device__ __align__(128) float    g_degI[NMAX];
__device__ __align__(128) int      g_cntO[NMAX];
__device__ __align__(128) int      g_cntI[NMAX];
__device__ __align__(128) int      g_off[NMAX];
__device__ __align__(128) int      g_cur[NMAX];
__device__ __align__(128) int      g_csrc[EMAX];
__device__ __align__(128) uint32_t g_ahi[(size_t)NMAX * 64];  // agg hi (packed bf16x2)
__device__ __align__(128) uint32_t g_alo[(size_t)NMAX * 64];  // agg lo
__device__ __align__(128) float    g_h[(size_t)NMAX * D];     // layer-1 output (fp32)
__device__ __align__(128) uint32_t g_w1hi[D * 64];
__device__ __align__(128) uint32_t g_w1lo[D * 64];
__device__ __align__(128) uint32_t g_w2hi[D * 64];
__device__ __align__(128) uint32_t g_w2lo[D * 64];
__device__ int g_is64;
__device__ int g_total;

// ---------------- prep0: zero counters + dtype probe + W split (one grid) --------
__global__ void k_prep0(const void* __restrict__ ei, int n, int FB,
                        const float* __restrict__ W1, const float* __restrict__ W2) {
    if (blockIdx.x < (unsigned)FB) {
        int i = blockIdx.x * blockDim.x + threadIdx.x;
        if (i < n) { g_cntO[i] = 0; g_cntI[i] = 0; }
        if (blockIdx.x == 0 && threadIdx.x == 0) {
            const long long* e64 = (const long long*)ei;
            int ok = 1;
            for (int k = 0; k < 16; k++) {
                long long v = e64[k];
                if (v < 0 || v >= (long long)n) ok = 0;
            }
            g_is64 = ok;   // int32 read as int64 packs random high word -> out of range
            g_total = 0;
        }
    } else {
        int i = (blockIdx.x - FB) * blockDim.x + threadIdx.x;  // 0..16383
        if (i >= 2 * D * 64) return;
        int which = i >= D * 64;
        int idx = which ? i - D * 64 : i;
        const float* W = which ? W2 : W1;
        float2 v = reinterpret_cast<const float2*>(W)[idx];
        __nv_bfloat162 h = __float22bfloat162_rn(make_float2(v.x, v.y));
        float lx = v.x - __bfloat162float(h.x);
        float ly = v.y - __bfloat162float(h.y);
        __nv_bfloat162 l = __float22bfloat162_rn(make_float2(lx, ly));
        uint32_t* hi = which ? g_w2hi : g_w1hi;
        uint32_t* lo = which ? g_w2lo : g_w1lo;
        hi[idx] = *reinterpret_cast<uint32_t*>(&h);
        lo[idx] = *reinterpret_cast<uint32_t*>(&l);
    }
}

// ---------------- degree count: 4 edges per thread, vectorized ----------------
__global__ void k_count(const void* __restrict__ ei, int E) {
    int q = blockIdx.x * blockDim.x + threadIdx.x;   // quad index over 2E
    int base = q * 4;
    if (base >= 2 * E) return;
    int v[4];
    int nv = min(4, 2 * E - base);
    if (g_is64) {
        const long long* e64 = (const long long*)ei;
        longlong2 p0 = *reinterpret_cast<const longlong2*>(e64 + base);
        v[0] = (int)p0.x; v[1] = (int)p0.y;
        if (nv > 2) {
            longlong2 p1 = *reinterpret_cast<const longlong2*>(e64 + base + 2);
            v[2] = (int)p1.x; v[3] = (int)p1.y;
        }
    } else {
        int4 p = *reinterpret_cast<const int4*>((const int*)ei + base);
        v[0] = p.x; v[1] = p.y; v[2] = p.z; v[3] = p.w;
    }
#pragma unroll
    for (int k = 0; k < 4; k++) {
        if (k >= nv) break;
        int i = base + k;
        if (i < E) atomicAdd(&g_cntO[v[k]], 1);
        else       atomicAdd(&g_cntI[v[k]], 1);
    }
}

// ---------------- alloc: fused block-scan offset allocation + degree finalize ----
__global__ void k_alloc(int n) {
    __shared__ int s[256];
    __shared__ int base;
    int i = blockIdx.x * 256 + threadIdx.x;
    int c = (i < n) ? g_cntI[i] : 0;
    s[threadIdx.x] = c;
    __syncthreads();
#pragma unroll
    for (int off = 1; off < 256; off <<= 1) {
        int t = (threadIdx.x >= off) ? s[threadIdx.x - off] : 0;
        __syncthreads();
        s[threadIdx.x] += t;
        __syncthreads();
    }
    if (threadIdx.x == 255) base = atomicAdd(&g_total, s[255]);
    __syncthreads();
    if (i < n) {
        int off = base + s[threadIdx.x] - c;
        g_off[i] = off;
        g_cur[i] = off;
        g_degO[i] = rsqrtf((float)max(g_cntO[i], 1));
        g_degI[i] = rsqrtf((float)max(g_cntI[i], 1));
    }
}

// ---------------- bucket: 2 edges per thread, vectorized (R13 proven) ----------
__global__ void k_bucket(const void* __restrict__ ei, int E) {
    int q = blockIdx.x * blockDim.x + threadIdx.x;
    int base = q * 2;
    if (base >= E) return;
    int r[2], c[2];
    int nv = min(2, E - base);
    if (g_is64) {
        const long long* e64 = (const long long*)ei;
        longlong2 pr = *reinterpret_cast<const longlong2*>(e64 + base);
        longlong2 pc = *reinterpret_cast<const longlong2*>(e64 + E + base);
        r[0] = (int)pr.x; r[1] = (int)pr.y;
        c[0] = (int)pc.x; c[1] = (int)pc.y;
    } else {
        int2 pr = *reinterpret_cast<const int2*>((const int*)ei + base);
        int2 pc = *reinterpret_cast<const int2*>((const int*)ei + E + base);
        r[0] = pr.x; r[1] = pr.y;
        c[0] = pc.x; c[1] = pc.y;
    }
#pragma unroll
    for (int k = 0; k < 2; k++) {
        if (k >= nv) break;
        int pos = atomicAdd(&g_cur[c[k]], 1);
        g_csrc[pos] = r[k];
    }
}

// ---------------- gather: agg[v] = sum src[u]*invO[u]; 8-edge unroll -------------
template <bool FROM_H>
__global__ void k_gather(const float* __restrict__ xin, int n) {
    int v = blockIdx.x * (blockDim.x >> 5) + (threadIdx.x >> 5);
    if (v >= n) return;
    int lane = threadIdx.x & 31;
    const float* src = FROM_H ? g_h : xin;
    int p = g_off[v];
    int end = p + g_cntI[v];
    float4 a0 = make_float4(0.f, 0.f, 0.f, 0.f);
    float4 a1 = make_float4(0.f, 0.f, 0.f, 0.f);
    float4 a2 = make_float4(0.f, 0.f, 0.f, 0.f);
    float4 a3 = make_float4(0.f, 0.f, 0.f, 0.f);
    for (; p + 7 < end; p += 8) {
        int u0 = g_csrc[p],     u1 = g_csrc[p + 1], u2 = g_csrc[p + 2], u3 = g_csrc[p + 3];
        int u4 = g_csrc[p + 4], u5 = g_csrc[p + 5], u6 = g_csrc[p + 6], u7 = g_csrc[p + 7];
        float s0 = g_degO[u0], s1 = g_degO[u1], s2 = g_degO[u2], s3 = g_degO[u3];
        float s4 = g_degO[u4], s5 = g_degO[u5], s6 = g_degO[u6], s7 = g_degO[u7];
        float4 va = reinterpret_cast<const float4*>(src + (size_t)u0 * D)[lane];
        float4 vb = reinterpret_cast<const float4*>(src + (size_t)u1 * D)[lane];
        float4 vc = reinterpret_cast<const float4*>(src + (size_t)u2 * D)[lane];
        float4 vd = reinterpret_cast<const float4*>(src + (size_t)u3 * D)[lane];
        float4 ve = reinterpret_cast<const float4*>(src + (size_t)u4 * D)[lane];
        float4 vf = reinterpret_cast<const float4*>(src + (size_t)u5 * D)[lane];
        float4 vg = reinterpret_cast<const float4*>(src + (size_t)u6 * D)[lane];
        float4 vh = reinterpret_cast<const float4*>(src + (size_t)u7 * D)[lane];
        a0.x += va.x * s0; a0.y += va.y * s0; a0.z += va.z * s0; a0.w += va.w * s0;
        a1.x += vb.x * s1; a1.y += vb.y * s1; a1.z += vb.z * s1; a1.w += vb.w * s1;
        a2.x += vc.x * s2; a2.y += vc.y * s2; a2.z += vc.z * s2; a2.w += vc.w * s2;
        a3.x += vd.x * s3; a3.y += vd.y * s3; a3.z += vd.z * s3; a3.w += vd.w * s3;
        a0.x += ve.x * s4; a0.y += ve.y * s4; a0.z += ve.z * s4; a0.w += ve.w * s4;
        a1.x += vf.x * s5; a1.y += vf.y * s5; a1.z += vf.z * s5; a1.w += vf.w * s5;
        a2.x += vg.x * s6; a2.y += vg.y * s6; a2.z += vg.z * s6; a2.w += vg.w * s6;
        a3.x += vh.x * s7; a3.y += vh.y * s7; a3.z += vh.z * s7; a3.w += vh.w * s7;
    }
    for (; p + 1 < end; p += 2) {
        int u0 = g_csrc[p], u1 = g_csrc[p + 1];
        float s0 = g_degO[u0], s1 = g_degO[u1];
        float4 va = reinterpret_cast<const float4*>(src + (size_t)u0 * D)[lane];
        float4 vb = reinterpret_cast<const float4*>(src + (size_t)u1 * D)[lane];
        a0.x += va.x * s0; a0.y += va.y * s0; a0.z += va.z * s0; a0.w += va.w * s0;
        a1.x += vb.x * s1; a1.y += vb.y * s1; a1.z += vb.z * s1; a1.w += vb.w * s1;
    }
    if (p < end) {
        int u0 = g_csrc[p];
        float s0 = g_degO[u0];
        float4 va = reinterpret_cast<const float4*>(src + (size_t)u0 * D)[lane];
        a0.x += va.x * s0; a0.y += va.y * s0; a0.z += va.z * s0; a0.w += va.w * s0;
    }
    a0.x += a1.x + a2.x + a3.x;
    a0.y += a1.y + a2.y + a3.y;
    a0.z += a1.z + a2.z + a3.z;
    a0.w += a1.w + a2.w + a3.w;

    __nv_bfloat162 h0 = __float22bfloat162_rn(make_float2(a0.x, a0.y));
    __nv_bfloat162 h1 = __float22bfloat162_rn(make_float2(a0.z, a0.w));
    __nv_bfloat162 l0 = __float22bfloat162_rn(make_float2(a0.x - __bfloat162float(h0.x),
                                                          a0.y - __bfloat162float(h0.y)));
    __nv_bfloat162 l1 = __float22bfloat162_rn(make_float2(a0.z - __bfloat162float(h1.x),
                                                          a0.w - __bfloat162float(h1.y)));
    uint2 hv = make_uint2(*reinterpret_cast<uint32_t*>(&h0), *reinterpret_cast<uint32_t*>(&h1));
    uint2 lv = make_uint2(*reinterpret_cast<uint32_t*>(&l0), *reinterpret_cast<uint32_t*>(&l1));
    reinterpret_cast<uint2*>(g_ahi + (size_t)v * 64)[lane] = hv;
    reinterpret_cast<uint2*>(g_alo + (size_t)v * 64)[lane] = lv;
}

// ================= bf16 split-3 MMA GEMM with ldmatrix fragments =================
__device__ __forceinline__ void mma_bf16(float* d, const uint32_t* a,
                                         uint32_t b0, uint32_t b1) {
    asm volatile(
        "mma.sync.aligned.m16n8k16.row.col.f32.bf16.bf16.f32 "
        "{%0,%1,%2,%3}, {%4,%5,%6,%7}, {%8,%9}, {%0,%1,%2,%3};"
        : "+f"(d[0]), "+f"(d[1]), "+f"(d[2]), "+f"(d[3])
        : "r"(a[0]), "r"(a[1]), "r"(a[2]), "r"(a[3]), "r"(b0), "r"(b1));
}
__device__ __forceinline__ void ldsm_x4(uint32_t* r, uint32_t addr) {
    asm volatile("ldmatrix.sync.aligned.m8n8.x4.shared.b16 {%0,%1,%2,%3}, [%4];"
                 : "=r"(r[0]), "=r"(r[1]), "=r"(r[2]), "=r"(r[3]) : "r"(addr));
}

// smem: Ahi(64x68) Alo(64x68) Whi(128x68) Wlo(128x68) u32 = 104448 B -> 2 CTA/SM
#define SMEM_MMA ((2 * 64 * PITCH + 2 * 128 * PITCH) * 4)

template <bool LAYER1>
__global__ __launch_bounds__(512, 2)
void k_gemm_mma(const float* __restrict__ bias,
                const float* __restrict__ xres, float* __restrict__ outp, int n) {
    extern __shared__ uint32_t sm[];
    uint32_t* Ahi = sm;
    uint32_t* Alo = sm + 64 * PITCH;
    uint32_t* Whi = sm + 2 * 64 * PITCH;
    uint32_t* Wlo = Whi + 128 * PITCH;

    const uint32_t* whi = LAYER1 ? g_w1hi : g_w2hi;
    const uint32_t* wlo = LAYER1 ? g_w1lo : g_w2lo;

    const int tid = threadIdx.x;
    const int warp = tid >> 5;
    const int lane = tid & 31;
    const int g = lane >> 2;
    const int t = lane & 3;
    const int p = warp & 7;        // n-pair (16 cols)
    const int mh = warp >> 3;      // m-half (32 rows)
    float* out = LAYER1 ? g_h : outp;

    const int lr = lane & 15;
    const int lh = (lane >> 4) * 4;
    const uint32_t sAhi = (uint32_t)__cvta_generic_to_shared(Ahi);
    const uint32_t sAlo = (uint32_t)__cvta_generic_to_shared(Alo);
    const uint32_t sWhi = (uint32_t)__cvta_generic_to_shared(Whi);
    const uint32_t sWlo = (uint32_t)__cvta_generic_to_shared(Wlo);
    const uint32_t bRowOff = (uint32_t)((p * 16 + lr) * PITCH + lh) * 4u;

    // ---- W fill once: 128 rows x 16 uint4, hi+lo ----
#pragma unroll
    for (int it = 0; it < 4; it++) {
        int idx = tid + it * 512;            // 0..2047
        int r = idx >> 4, c = idx & 15;
        *reinterpret_cast<uint4*>(Whi + r * PITCH + c * 4) =
            reinterpret_cast<const uint4*>(whi + r * 64)[c];
        *reinterpret_cast<uint4*>(Wlo + r * PITCH + c * 4) =
            reinterpret_cast<const uint4*>(wlo + r * 64)[c];
    }

    // ---- two 64-row tiles per CTA ----
#pragma unroll
    for (int tile = 0; tile < 2; tile++) {
        const int rowBase = blockIdx.x * 128 + tile * 64;

        // A fill: 64 rows x 16 uint4, hi+lo
#pragma unroll
        for (int it = 0; it < 2; it++) {
            int idx = tid + it * 512;        // 0..1023
            int r = idx >> 4, c = idx & 15;
            int grow = rowBase + r;
            uint4 vh = make_uint4(0u, 0u, 0u, 0u), vl = vh;
            if (grow < n) {
                vh = reinterpret_cast<const uint4*>(g_ahi + (size_t)grow * 64)[c];
                vl = reinterpret_cast<const uint4*>(g_alo + (size_t)grow * 64)[c];
            }
            *reinterpret_cast<uint4*>(Ahi + r * PITCH + c * 4) = vh;
            *reinterpret_cast<uint4*>(Alo + r * PITCH + c * 4) = vl;
        }
        __syncthreads();

        float acc[2][2][4];
#pragma unroll
        for (int mt = 0; mt < 2; mt++)
#pragma unroll
            for (int nt = 0; nt < 2; nt++)
#pragma unroll
                for (int q = 0; q < 4; q++) acc[mt][nt][q] = 0.f;

#pragma unroll
        for (int kt = 0; kt < 8; kt++) {
            const uint32_t kb4 = (uint32_t)(kt * 8) * 4u;
            uint32_t bh[4], bl[4];
            ldsm_x4(bh, sWhi + bRowOff + kb4);
            ldsm_x4(bl, sWlo + bRowOff + kb4);
#pragma unroll
            for (int mt = 0; mt < 2; mt++) {
                const uint32_t aOff =
                    (uint32_t)((mh * 32 + mt * 16 + lr) * PITCH + lh) * 4u + kb4;
                uint32_t ah[4], al[4];
                ldsm_x4(ah, sAhi + aOff);
                ldsm_x4(al, sAlo + aOff);
#pragma unroll
                for (int nt = 0; nt < 2; nt++) {
                    mma_bf16(acc[mt][nt], ah, bh[nt], bh[2 + nt]);   // hi*hi
                    mma_bf16(acc[mt][nt], al, bh[nt], bh[2 + nt]);   // lo*hi
                    mma_bf16(acc[mt][nt], ah, bl[nt], bl[2 + nt]);   // hi*lo
                }
            }
        }
        __syncthreads();

        // epilogue for this tile
#pragma unroll
        for (int nt = 0; nt < 2; nt++) {
            int col = p * 16 + nt * 8 + 2 * t;
            float2 b2 = *reinterpret_cast<const float2*>(bias + col);
#pragma unroll
            for (int mt = 0; mt < 2; mt++) {
                int r0 = rowBase + mh * 32 + mt * 16 + g;
                int r1 = r0 + 8;
                if (r0 < n) {
                    float inv = g_degI[r0];
                    float o0 = (acc[mt][nt][0] + b2.x) * inv;
                    float o1 = (acc[mt][nt][1] + b2.y) * inv;
                    if (LAYER1) {
                        float2 x2 = *reinterpret_cast<const float2*>(xres + (size_t)r0 * D + col);
                        o0 = fmaxf(o0 + x2.x, 0.f);
                        o1 = fmaxf(o1 + x2.y, 0.f);
                    }
                    *reinterpret_cast<float2*>(out + (size_t)r0 * D + col) = make_float2(o0, o1);
                }
                if (r1 < n) {
                    float inv = g_degI[r1];
                    float o0 = (acc[mt][nt][2] + b2.x) * inv;
                    float o1 = (acc[mt][nt][3] + b2.y) * inv;
                    if (LAYER1) {
                        float2 x2 = *reinterpret_cast<const float2*>(xres + (size_t)r1 * D + col);
                        o0 = fmaxf(o0 + x2.x, 0.f);
                        o1 = fmaxf(o1 + x2.y, 0.f);
                    }
                    *reinterpret_cast<float2*>(out + (size_t)r1 * D + col) = make_float2(o0, o1);
                }
            }
        }
    }
}

// ---------------- launch ----------------
extern "C" void kernel_launch(void* const* d_in, const int* in_sizes, int n_in,
                              void* d_out, int out_size) {
    const float* x  = (const float*)d_in[0];
    const void*  ei = d_in[1];
    const float* W1 = (const float*)d_in[2];
    const float* b1 = (const float*)d_in[3];
    const float* W2 = (const float*)d_in[4];
    const float* b2 = (const float*)d_in[5];
    float* out      = (float*)d_out;

    const int n = in_sizes[0] / D;   // 100000
    const int E = in_sizes[1] / 2;   // 800000

    const int FB = (n + 255) / 256;
    const int NB = (n + 255) / 256;
    const int GAB = (n + 7) / 8;
    const int GB = (n + 127) / 128;

    cudaFuncSetAttribute(k_gemm_mma<true>,  cudaFuncAttributeMaxDynamicSharedMemorySize, SMEM_MMA);
    cudaFuncSetAttribute(k_gemm_mma<false>, cudaFuncAttributeMaxDynamicSharedMemorySize, SMEM_MMA);

    // prep (4 launches)
    k_prep0<<<FB + 64, 256>>>(ei, n, FB, W1, W2);
    k_count<<<(2 * E / 4 + 255) / 256, 256>>>(ei, E);
    k_alloc<<<NB, 256>>>(n);
    k_bucket<<<(E / 2 + 255) / 256, 256>>>(ei, E);

    // layer 1: gather -> (ahi, alo); h = relu((agg@W1^T + b1)*invI + x)
    k_gather<false><<<GAB, 256>>>(x, n);
    k_gemm_mma<true><<<GB, 512, SMEM_MMA>>>(b1, x, nullptr, n);

    // layer 2: gather(h) -> (ahi, alo); out = (agg@W2^T + b2)*invI
    k_gather<true><<<GAB, 256>>>(nullptr, n);
    k_gemm_mma<false><<<GB, 512, SMEM_MMA>>>(b2, nullptr, out, n);
}

// round 16
// speedup vs baseline: 1.1359x; 1.1359x over previous
#include <cuda_runtime.h>
#include <cuda_bf16.h>
#include <cstdint>
#include <cstddef>

#define D 128
#define NMAX 100096   // multiple of 128
#define EMAX 800000
#define PITCH 68      // u32 per smem row (136 bf16): ldmatrix conflict-free

// ---------------- scratch (device globals; no allocation allowed) ----------------
__device__ __align__(128) float    g_degO[NMAX];
__device__ __align__(128) float    g_degI[NMAX];
__device__ __align__(128) int      g_cntO[NMAX];
__device__ __align__(128) int      g_cntI[NMAX];
__device__ __align__(128) int      g_off[NMAX];
__device__ __align__(128) int      g_cur[NMAX];
__device__ __align__(128) int      g_csrc[EMAX];
__device__ __align__(128) uint32_t g_ahi[(size_t)NMAX * 64];  // agg hi (packed bf16x2)
__device__ __align__(128) uint32_t g_alo[(size_t)NMAX * 64];  // agg lo
__device__ __align__(128) float    g_h[(size_t)NMAX * D];     // layer-1 out, PRE-SCALED by degO
__device__ __align__(128) uint32_t g_w1hi[D * 64];
__device__ __align__(128) uint32_t g_w1lo[D * 64];
__device__ __align__(128) uint32_t g_w2hi[D * 64];
__device__ __align__(128) uint32_t g_w2lo[D * 64];
__device__ int g_is64;
__device__ int g_total;

// ---------------- prep0: zero counters + dtype probe + W split (one grid) --------
__global__ void k_prep0(const void* __restrict__ ei, int n, int FB,
                        const float* __restrict__ W1, const float* __restrict__ W2) {
    if (blockIdx.x < (unsigned)FB) {
        int i = blockIdx.x * blockDim.x + threadIdx.x;
        if (i < n) { g_cntO[i] = 0; g_cntI[i] = 0; }
        if (blockIdx.x == 0 && threadIdx.x == 0) {
            const long long* e64 = (const long long*)ei;
            int ok = 1;
            for (int k = 0; k < 16; k++) {
                long long v = e64[k];
                if (v < 0 || v >= (long long)n) ok = 0;
            }
            g_is64 = ok;   // int32 read as int64 packs random high word -> out of range
            g_total = 0;
        }
    } else {
        int i = (blockIdx.x - FB) * blockDim.x + threadIdx.x;  // 0..16383
        if (i >= 2 * D * 64) return;
        int which = i >= D * 64;
        int idx = which ? i - D * 64 : i;
        const float* W = which ? W2 : W1;
        float2 v = reinterpret_cast<const float2*>(W)[idx];
        __nv_bfloat162 h = __float22bfloat162_rn(make_float2(v.x, v.y));
        float lx = v.x - __bfloat162float(h.x);
        float ly = v.y - __bfloat162float(h.y);
        __nv_bfloat162 l = __float22bfloat162_rn(make_float2(lx, ly));
        uint32_t* hi = which ? g_w2hi : g_w1hi;
        uint32_t* lo = which ? g_w2lo : g_w1lo;
        hi[idx] = *reinterpret_cast<uint32_t*>(&h);
        lo[idx] = *reinterpret_cast<uint32_t*>(&l);
    }
}

// ---------------- degree count: 4 edges per thread, vectorized ----------------
__global__ void k_count(const void* __restrict__ ei, int E) {
    int q = blockIdx.x * blockDim.x + threadIdx.x;   // quad index over 2E
    int base = q * 4;
    if (base >= 2 * E) return;
    int v[4];
    int nv = min(4, 2 * E - base);
    if (g_is64) {
        const long long* e64 = (const long long*)ei;
        longlong2 p0 = *reinterpret_cast<const longlong2*>(e64 + base);
        v[0] = (int)p0.x; v[1] = (int)p0.y;
        if (nv > 2) {
            longlong2 p1 = *reinterpret_cast<const longlong2*>(e64 + base + 2);
            v[2] = (int)p1.x; v[3] = (int)p1.y;
        }
    } else {
        int4 p = *reinterpret_cast<const int4*>((const int*)ei + base);
        v[0] = p.x; v[1] = p.y; v[2] = p.z; v[3] = p.w;
    }
#pragma unroll
    for (int k = 0; k < 4; k++) {
        if (k >= nv) break;
        int i = base + k;
        if (i < E) atomicAdd(&g_cntO[v[k]], 1);
        else       atomicAdd(&g_cntI[v[k]], 1);
    }
}

// ---------------- alloc: fused block-scan offset allocation + degree finalize ----
__global__ void k_alloc(int n) {
    __shared__ int s[256];
    __shared__ int base;
    int i = blockIdx.x * 256 + threadIdx.x;
    int c = (i < n) ? g_cntI[i] : 0;
    s[threadIdx.x] = c;
    __syncthreads();
#pragma unroll
    for (int off = 1; off < 256; off <<= 1) {
        int t = (threadIdx.x >= off) ? s[threadIdx.x - off] : 0;
        __syncthreads();
        s[threadIdx.x] += t;
        __syncthreads();
    }
    if (threadIdx.x == 255) base = atomicAdd(&g_total, s[255]);
    __syncthreads();
    if (i < n) {
        int off = base + s[threadIdx.x] - c;
        g_off[i] = off;
        g_cur[i] = off;
        g_degO[i] = rsqrtf((float)max(g_cntO[i], 1));
        g_degI[i] = rsqrtf((float)max(g_cntI[i], 1));
    }
}

// ---------------- bucket: 2 edges per thread, vectorized (R13 proven) ----------
__global__ void k_bucket(const void* __restrict__ ei, int E) {
    int q = blockIdx.x * blockDim.x + threadIdx.x;
    int base = q * 2;
    if (base >= E) return;
    int r[2], c[2];
    int nv = min(2, E - base);
    if (g_is64) {
        const long long* e64 = (const long long*)ei;
        longlong2 pr = *reinterpret_cast<const longlong2*>(e64 + base);
        longlong2 pc = *reinterpret_cast<const longlong2*>(e64 + E + base);
        r[0] = (int)pr.x; r[1] = (int)pr.y;
        c[0] = (int)pc.x; c[1] = (int)pc.y;
    } else {
        int2 pr = *reinterpret_cast<const int2*>((const int*)ei + base);
        int2 pc = *reinterpret_cast<const int2*>((const int*)ei + E + base);
        r[0] = pr.x; r[1] = pr.y;
        c[0] = pc.x; c[1] = pc.y;
    }
#pragma unroll
    for (int k = 0; k < 2; k++) {
        if (k >= nv) break;
        int pos = atomicAdd(&g_cur[c[k]], 1);
        g_csrc[pos] = r[k];
    }
}

// ---------------- gather: agg[v] = sum over in-edges; 4-edge unroll (R13) --------
// SCALED: multiply each source row by degO[u] (layer 1; x is unscaled).
// !SCALED: source rows are pre-scaled (layer 2; h' = h*degO written by epilogue).
template <bool FROM_H, bool SCALED>
__global__ void k_gather(const float* __restrict__ xin, int n) {
    int v = blockIdx.x * (blockDim.x >> 5) + (threadIdx.x >> 5);
    if (v >= n) return;
    int lane = threadIdx.x & 31;
    const float* src = FROM_H ? g_h : xin;
    int p = g_off[v];
    int end = p + g_cntI[v];
    float4 a0 = make_float4(0.f, 0.f, 0.f, 0.f);
    float4 a1 = make_float4(0.f, 0.f, 0.f, 0.f);
    for (; p + 3 < end; p += 4) {
        int u0 = g_csrc[p], u1 = g_csrc[p + 1], u2 = g_csrc[p + 2], u3 = g_csrc[p + 3];
        float s0 = SCALED ? g_degO[u0] : 1.f;
        float s1 = SCALED ? g_degO[u1] : 1.f;
        float s2 = SCALED ? g_degO[u2] : 1.f;
        float s3 = SCALED ? g_degO[u3] : 1.f;
        float4 a = reinterpret_cast<const float4*>(src + (size_t)u0 * D)[lane];
        float4 b = reinterpret_cast<const float4*>(src + (size_t)u1 * D)[lane];
        float4 c = reinterpret_cast<const float4*>(src + (size_t)u2 * D)[lane];
        float4 d = reinterpret_cast<const float4*>(src + (size_t)u3 * D)[lane];
        if (SCALED) {
            a0.x += a.x * s0; a0.y += a.y * s0; a0.z += a.z * s0; a0.w += a.w * s0;
            a1.x += b.x * s1; a1.y += b.y * s1; a1.z += b.z * s1; a1.w += b.w * s1;
            a0.x += c.x * s2; a0.y += c.y * s2; a0.z += c.z * s2; a0.w += c.w * s2;
            a1.x += d.x * s3; a1.y += d.y * s3; a1.z += d.z * s3; a1.w += d.w * s3;
        } else {
            a0.x += a.x; a0.y += a.y; a0.z += a.z; a0.w += a.w;
            a1.x += b.x; a1.y += b.y; a1.z += b.z; a1.w += b.w;
            a0.x += c.x; a0.y += c.y; a0.z += c.z; a0.w += c.w;
            a1.x += d.x; a1.y += d.y; a1.z += d.z; a1.w += d.w;
        }
    }
    for (; p < end; p++) {
        int u0 = g_csrc[p];
        float s0 = SCALED ? g_degO[u0] : 1.f;
        float4 a = reinterpret_cast<const float4*>(src + (size_t)u0 * D)[lane];
        if (SCALED) {
            a0.x += a.x * s0; a0.y += a.y * s0; a0.z += a.z * s0; a0.w += a.w * s0;
        } else {
            a0.x += a.x; a0.y += a.y; a0.z += a.z; a0.w += a.w;
        }
    }
    a0.x += a1.x; a0.y += a1.y; a0.z += a1.z; a0.w += a1.w;

    __nv_bfloat162 h0 = __float22bfloat162_rn(make_float2(a0.x, a0.y));
    __nv_bfloat162 h1 = __float22bfloat162_rn(make_float2(a0.z, a0.w));
    __nv_bfloat162 l0 = __float22bfloat162_rn(make_float2(a0.x - __bfloat162float(h0.x),
                                                          a0.y - __bfloat162float(h0.y)));
    __nv_bfloat162 l1 = __float22bfloat162_rn(make_float2(a0.z - __bfloat162float(h1.x),
                                                          a0.w - __bfloat162float(h1.y)));
    uint2 hv = make_uint2(*reinterpret_cast<uint32_t*>(&h0), *reinterpret_cast<uint32_t*>(&h1));
    uint2 lv = make_uint2(*reinterpret_cast<uint32_t*>(&l0), *reinterpret_cast<uint32_t*>(&l1));
    reinterpret_cast<uint2*>(g_ahi + (size_t)v * 64)[lane] = hv;
    reinterpret_cast<uint2*>(g_alo + (size_t)v * 64)[lane] = lv;
}

// ================= bf16 split-3 MMA GEMM with ldmatrix fragments =================
__device__ __forceinline__ void mma_bf16(float* d, const uint32_t* a,
                                         uint32_t b0, uint32_t b1) {
    asm volatile(
        "mma.sync.aligned.m16n8k16.row.col.f32.bf16.bf16.f32 "
        "{%0,%1,%2,%3}, {%4,%5,%6,%7}, {%8,%9}, {%0,%1,%2,%3};"
        : "+f"(d[0]), "+f"(d[1]), "+f"(d[2]), "+f"(d[3])
        : "r"(a[0]), "r"(a[1]), "r"(a[2]), "r"(a[3]), "r"(b0), "r"(b1));
}
__device__ __forceinline__ void ldsm_x4(uint32_t* r, uint32_t addr) {
    asm volatile("ldmatrix.sync.aligned.m8n8.x4.shared.b16 {%0,%1,%2,%3}, [%4];"
                 : "=r"(r[0]), "=r"(r[1]), "=r"(r[2]), "=r"(r[3]) : "r"(addr));
}

// smem: Ahi(64x68) Alo(64x68) Whi(128x68) Wlo(128x68) u32 = 104448 B -> 2 CTA/SM
#define SMEM_MMA ((2 * 64 * PITCH + 2 * 128 * PITCH) * 4)

// LAYER1 epilogue: h' = relu((agg@W1^T + b1)*invI + x) * degO[row]  (pre-scale for gather-2)
template <bool LAYER1>
__global__ __launch_bounds__(512, 2)
void k_gemm_mma(const float* __restrict__ bias,
                const float* __restrict__ xres, float* __restrict__ outp, int n) {
    extern __shared__ uint32_t sm[];
    uint32_t* Ahi = sm;
    uint32_t* Alo = sm + 64 * PITCH;
    uint32_t* Whi = sm + 2 * 64 * PITCH;
    uint32_t* Wlo = Whi + 128 * PITCH;

    const uint32_t* whi = LAYER1 ? g_w1hi : g_w2hi;
    const uint32_t* wlo = LAYER1 ? g_w1lo : g_w2lo;

    const int tid = threadIdx.x;
    const int warp = tid >> 5;
    const int lane = tid & 31;
    const int g = lane >> 2;
    const int t = lane & 3;
    const int p = warp & 7;        // n-pair (16 cols)
    const int mh = warp >> 3;      // m-half (32 rows)
    float* out = LAYER1 ? g_h : outp;

    const int lr = lane & 15;
    const int lh = (lane >> 4) * 4;
    const uint32_t sAhi = (uint32_t)__cvta_generic_to_shared(Ahi);
    const uint32_t sAlo = (uint32_t)__cvta_generic_to_shared(Alo);
    const uint32_t sWhi = (uint32_t)__cvta_generic_to_shared(Whi);
    const uint32_t sWlo = (uint32_t)__cvta_generic_to_shared(Wlo);
    const uint32_t bRowOff = (uint32_t)((p * 16 + lr) * PITCH + lh) * 4u;

    // ---- W fill once: 128 rows x 16 uint4, hi+lo ----
#pragma unroll
    for (int it = 0; it < 4; it++) {
        int idx = tid + it * 512;            // 0..2047
        int r = idx >> 4, c = idx & 15;
        *reinterpret_cast<uint4*>(Whi + r * PITCH + c * 4) =
            reinterpret_cast<const uint4*>(whi + r * 64)[c];
        *reinterpret_cast<uint4*>(Wlo + r * PITCH + c * 4) =
            reinterpret_cast<const uint4*>(wlo + r * 64)[c];
    }

    // ---- two 64-row tiles per CTA ----
#pragma unroll
    for (int tile = 0; tile < 2; tile++) {
        const int rowBase = blockIdx.x * 128 + tile * 64;

        // A fill: 64 rows x 16 uint4, hi+lo
#pragma unroll
        for (int it = 0; it < 2; it++) {
            int idx = tid + it * 512;        // 0..1023
            int r = idx >> 4, c = idx & 15;
            int grow = rowBase + r;
            uint4 vh = make_uint4(0u, 0u, 0u, 0u), vl = vh;
            if (grow < n) {
                vh = reinterpret_cast<const uint4*>(g_ahi + (size_t)grow * 64)[c];
                vl = reinterpret_cast<const uint4*>(g_alo + (size_t)grow * 64)[c];
            }
            *reinterpret_cast<uint4*>(Ahi + r * PITCH + c * 4) = vh;
            *reinterpret_cast<uint4*>(Alo + r * PITCH + c * 4) = vl;
        }
        __syncthreads();

        float acc[2][2][4];
#pragma unroll
        for (int mt = 0; mt < 2; mt++)
#pragma unroll
            for (int nt = 0; nt < 2; nt++)
#pragma unroll
                for (int q = 0; q < 4; q++) acc[mt][nt][q] = 0.f;

#pragma unroll
        for (int kt = 0; kt < 8; kt++) {
            const uint32_t kb4 = (uint32_t)(kt * 8) * 4u;
            uint32_t bh[4], bl[4];
            ldsm_x4(bh, sWhi + bRowOff + kb4);
            ldsm_x4(bl, sWlo + bRowOff + kb4);
#pragma unroll
            for (int mt = 0; mt < 2; mt++) {
                const uint32_t aOff =
                    (uint32_t)((mh * 32 + mt * 16 + lr) * PITCH + lh) * 4u + kb4;
                uint32_t ah[4], al[4];
                ldsm_x4(ah, sAhi + aOff);
                ldsm_x4(al, sAlo + aOff);
#pragma unroll
                for (int nt = 0; nt < 2; nt++) {
                    mma_bf16(acc[mt][nt], ah, bh[nt], bh[2 + nt]);   // hi*hi
                    mma_bf16(acc[mt][nt], al, bh[nt], bh[2 + nt]);   // lo*hi
                    mma_bf16(acc[mt][nt], ah, bl[nt], bl[2 + nt]);   // hi*lo
                }
            }
        }
        __syncthreads();

        // epilogue for this tile
#pragma unroll
        for (int nt = 0; nt < 2; nt++) {
            int col = p * 16 + nt * 8 + 2 * t;
            float2 b2 = *reinterpret_cast<const float2*>(bias + col);
#pragma unroll
            for (int mt = 0; mt < 2; mt++) {
                int r0 = rowBase + mh * 32 + mt * 16 + g;
                int r1 = r0 + 8;
                if (r0 < n) {
                    float inv = g_degI[r0];
                    float o0 = (acc[mt][nt][0] + b2.x) * inv;
                    float o1 = (acc[mt][nt][1] + b2.y) * inv;
                    if (LAYER1) {
                        float2 x2 = *reinterpret_cast<const float2*>(xres + (size_t)r0 * D + col);
                        float so = g_degO[r0];
                        o0 = fmaxf(o0 + x2.x, 0.f) * so;
                        o1 = fmaxf(o1 + x2.y, 0.f) * so;
                    }
                    *reinterpret_cast<float2*>(out + (size_t)r0 * D + col) = make_float2(o0, o1);
                }
                if (r1 < n) {
                    float inv = g_degI[r1];
                    float o0 = (acc[mt][nt][2] + b2.x) * inv;
                    float o1 = (acc[mt][nt][3] + b2.y) * inv;
                    if (LAYER1) {
                        float2 x2 = *reinterpret_cast<const float2*>(xres + (size_t)r1 * D + col);
                        float so = g_degO[r1];
                        o0 = fmaxf(o0 + x2.x, 0.f) * so;
                        o1 = fmaxf(o1 + x2.y, 0.f) * so;
                    }
                    *reinterpret_cast<float2*>(out + (size_t)r1 * D + col) = make_float2(o0, o1);
                }
            }
        }
    }
}

// ---------------- launch ----------------
extern "C" void kernel_launch(void* const* d_in, const int* in_sizes, int n_in,
                              void* d_out, int out_size) {
    const float* x  = (const float*)d_in[0];
    const void*  ei = d_in[1];
    const float* W1 = (const float*)d_in[2];
    const float* b1 = (const float*)d_in[3];
    const float* W2 = (const float*)d_in[4];
    const float* b2 = (const float*)d_in[5];
    float* out      = (float*)d_out;

    const int n = in_sizes[0] / D;   // 100000
    const int E = in_sizes[1] / 2;   // 800000

    const int FB = (n + 255) / 256;
    const int NB = (n + 255) / 256;
    const int GAB = (n + 7) / 8;
    const int GB = (n + 127) / 128;

    cudaFuncSetAttribute(k_gemm_mma<true>,  cudaFuncAttributeMaxDynamicSharedMemorySize, SMEM_MMA);
    cudaFuncSetAttribute(k_gemm_mma<false>, cudaFuncAttributeMaxDynamicSharedMemorySize, SMEM_MMA);

    // prep (4 launches)
    k_prep0<<<FB + 64, 256>>>(ei, n, FB, W1, W2);
    k_count<<<(2 * E / 4 + 255) / 256, 256>>>(ei, E);
    k_alloc<<<NB, 256>>>(n);
    k_bucket<<<(E / 2 + 255) / 256, 256>>>(ei, E);

    // layer 1: gather(x * degO) -> (ahi, alo); h' = relu((agg@W1^T+b1)*invI + x) * degO
    k_gather<false, true><<<GAB, 256>>>(x, n);
    k_gemm_mma<true><<<GB, 512, SMEM_MMA>>>(b1, x, nullptr, n);

    // layer 2: gather(h', pre-scaled) -> (ahi, alo); out = (agg@W2^T + b2)*invI
    k_gather<true, false><<<GAB, 256>>>(nullptr, n);
    k_gemm_mma<false><<<GB, 512, SMEM_MMA>>>(b2, nullptr, out, n);
}

// round 17
// speedup vs baseline: 1.1880x; 1.0460x over previous
#include <cuda_runtime.h>
#include <cuda_bf16.h>
#include <cstdint>
#include <cstddef>

#define D 128
#define NMAX 100096   // multiple of 128
#define EMAX 800000
#define PITCH 68      // u32 per smem row (136 bf16): ldmatrix conflict-free

// ---------------- scratch (device globals; no allocation allowed) ----------------
__device__ __align__(128) float    g_degO[NMAX];
__device__ __align__(128) float    g_degI[NMAX];
__device__ __align__(128) int      g_cntO[NMAX];
__device__ __align__(128) int      g_cntI[NMAX];
__device__ __align__(128) int      g_off[NMAX];
__device__ __align__(128) int      g_cur[NMAX];
__device__ __align__(128) int      g_csrc[EMAX];
__device__ __align__(128) uint32_t g_ahi[(size_t)NMAX * 64];  // agg hi (packed bf16x2)
__device__ __align__(128) uint32_t g_alo[(size_t)NMAX * 64];  // agg lo
__device__ __align__(128) float    g_h[(size_t)NMAX * D];     // layer-1 output (fp32)
__device__ __align__(128) uint32_t g_w1hi[D * 64];
__device__ __align__(128) uint32_t g_w1lo[D * 64];
__device__ __align__(128) uint32_t g_w2hi[D * 64];
__device__ __align__(128) uint32_t g_w2lo[D * 64];
__device__ int g_is64;
__device__ int g_total;

// ---------------- prep0: zero counters + dtype probe + W split (one grid) --------
__global__ void k_prep0(const void* __restrict__ ei, int n, int FB,
                        const float* __restrict__ W1, const float* __restrict__ W2) {
    if (blockIdx.x < (unsigned)FB) {
        int i = blockIdx.x * blockDim.x + threadIdx.x;
        if (i < n) { g_cntO[i] = 0; g_cntI[i] = 0; }
        if (blockIdx.x == 0 && threadIdx.x == 0) {
            const long long* e64 = (const long long*)ei;
            int ok = 1;
            for (int k = 0; k < 16; k++) {
                long long v = e64[k];
                if (v < 0 || v >= (long long)n) ok = 0;
            }
            g_is64 = ok;   // int32 read as int64 packs random high word -> out of range
            g_total = 0;
        }
    } else {
        int i = (blockIdx.x - FB) * blockDim.x + threadIdx.x;  // 0..16383
        if (i >= 2 * D * 64) return;
        int which = i >= D * 64;
        int idx = which ? i - D * 64 : i;
        const float* W = which ? W2 : W1;
        float2 v = reinterpret_cast<const float2*>(W)[idx];
        __nv_bfloat162 h = __float22bfloat162_rn(make_float2(v.x, v.y));
        float lx = v.x - __bfloat162float(h.x);
        float ly = v.y - __bfloat162float(h.y);
        __nv_bfloat162 l = __float22bfloat162_rn(make_float2(lx, ly));
        uint32_t* hi = which ? g_w2hi : g_w1hi;
        uint32_t* lo = which ? g_w2lo : g_w1lo;
        hi[idx] = *reinterpret_cast<uint32_t*>(&h);
        lo[idx] = *reinterpret_cast<uint32_t*>(&l);
    }
}

// ---------------- degree count: 4 edges per thread, vectorized ----------------
__global__ void k_count(const void* __restrict__ ei, int E) {
    int q = blockIdx.x * blockDim.x + threadIdx.x;   // quad index over 2E
    int base = q * 4;
    if (base >= 2 * E) return;
    int v[4];
    int nv = min(4, 2 * E - base);
    if (g_is64) {
        const long long* e64 = (const long long*)ei;
        longlong2 p0 = *reinterpret_cast<const longlong2*>(e64 + base);
        v[0] = (int)p0.x; v[1] = (int)p0.y;
        if (nv > 2) {
            longlong2 p1 = *reinterpret_cast<const longlong2*>(e64 + base + 2);
            v[2] = (int)p1.x; v[3] = (int)p1.y;
        }
    } else {
        int4 p = *reinterpret_cast<const int4*>((const int*)ei + base);
        v[0] = p.x; v[1] = p.y; v[2] = p.z; v[3] = p.w;
    }
#pragma unroll
    for (int k = 0; k < 4; k++) {
        if (k >= nv) break;
        int i = base + k;
        if (i < E) atomicAdd(&g_cntO[v[k]], 1);
        else       atomicAdd(&g_cntI[v[k]], 1);
    }
}

// ---------------- alloc: fused block-scan offset allocation + degree finalize ----
__global__ void k_alloc(int n) {
    __shared__ int s[256];
    __shared__ int base;
    int i = blockIdx.x * 256 + threadIdx.x;
    int c = (i < n) ? g_cntI[i] : 0;
    s[threadIdx.x] = c;
    __syncthreads();
#pragma unroll
    for (int off = 1; off < 256; off <<= 1) {
        int t = (threadIdx.x >= off) ? s[threadIdx.x - off] : 0;
        __syncthreads();
        s[threadIdx.x] += t;
        __syncthreads();
    }
    if (threadIdx.x == 255) base = atomicAdd(&g_total, s[255]);
    __syncthreads();
    if (i < n) {
        int off = base + s[threadIdx.x] - c;
        g_off[i] = off;
        g_cur[i] = off;
        g_degO[i] = rsqrtf((float)max(g_cntO[i], 1));
        g_degI[i] = rsqrtf((float)max(g_cntI[i], 1));
    }
}

// ---------------- bucket: 2 edges per thread, vectorized (R13 proven) ----------
__global__ void k_bucket(const void* __restrict__ ei, int E) {
    int q = blockIdx.x * blockDim.x + threadIdx.x;
    int base = q * 2;
    if (base >= E) return;
    int r[2], c[2];
    int nv = min(2, E - base);
    if (g_is64) {
        const long long* e64 = (const long long*)ei;
        longlong2 pr = *reinterpret_cast<const longlong2*>(e64 + base);
        longlong2 pc = *reinterpret_cast<const longlong2*>(e64 + E + base);
        r[0] = (int)pr.x; r[1] = (int)pr.y;
        c[0] = (int)pc.x; c[1] = (int)pc.y;
    } else {
        int2 pr = *reinterpret_cast<const int2*>((const int*)ei + base);
        int2 pc = *reinterpret_cast<const int2*>((const int*)ei + E + base);
        r[0] = pr.x; r[1] = pr.y;
        c[0] = pc.x; c[1] = pc.y;
    }
#pragma unroll
    for (int k = 0; k < 2; k++) {
        if (k >= nv) break;
        int pos = atomicAdd(&g_cur[c[k]], 1);
        g_csrc[pos] = r[k];
    }
}

// ---------------- gather: agg[v] = sum src[u]*invO[u]; 4-edge unroll (R13) -------
template <bool FROM_H>
__global__ void k_gather(const float* __restrict__ xin, int n) {
    int v = blockIdx.x * (blockDim.x >> 5) + (threadIdx.x >> 5);
    if (v >= n) return;
    int lane = threadIdx.x & 31;
    const float* src = FROM_H ? g_h : xin;
    int p = g_off[v];
    int end = p + g_cntI[v];
    float4 a0 = make_float4(0.f, 0.f, 0.f, 0.f);
    float4 a1 = make_float4(0.f, 0.f, 0.f, 0.f);
    for (; p + 3 < end; p += 4) {
        int u0 = g_csrc[p], u1 = g_csrc[p + 1], u2 = g_csrc[p + 2], u3 = g_csrc[p + 3];
        float s0 = g_degO[u0], s1 = g_degO[u1], s2 = g_degO[u2], s3 = g_degO[u3];
        float4 a = reinterpret_cast<const float4*>(src + (size_t)u0 * D)[lane];
        float4 b = reinterpret_cast<const float4*>(src + (size_t)u1 * D)[lane];
        float4 c = reinterpret_cast<const float4*>(src + (size_t)u2 * D)[lane];
        float4 d = reinterpret_cast<const float4*>(src + (size_t)u3 * D)[lane];
        a0.x += a.x * s0; a0.y += a.y * s0; a0.z += a.z * s0; a0.w += a.w * s0;
        a1.x += b.x * s1; a1.y += b.y * s1; a1.z += b.z * s1; a1.w += b.w * s1;
        a0.x += c.x * s2; a0.y += c.y * s2; a0.z += c.z * s2; a0.w += c.w * s2;
        a1.x += d.x * s3; a1.y += d.y * s3; a1.z += d.z * s3; a1.w += d.w * s3;
    }
    for (; p < end; p++) {
        int u0 = g_csrc[p];
        float s0 = g_degO[u0];
        float4 a = reinterpret_cast<const float4*>(src + (size_t)u0 * D)[lane];
        a0.x += a.x * s0; a0.y += a.y * s0; a0.z += a.z * s0; a0.w += a.w * s0;
    }
    a0.x += a1.x; a0.y += a1.y; a0.z += a1.z; a0.w += a1.w;

    __nv_bfloat162 h0 = __float22bfloat162_rn(make_float2(a0.x, a0.y));
    __nv_bfloat162 h1 = __float22bfloat162_rn(make_float2(a0.z, a0.w));
    __nv_bfloat162 l0 = __float22bfloat162_rn(make_float2(a0.x - __bfloat162float(h0.x),
                                                          a0.y - __bfloat162float(h0.y)));
    __nv_bfloat162 l1 = __float22bfloat162_rn(make_float2(a0.z - __bfloat162float(h1.x),
                                                          a0.w - __bfloat162float(h1.y)));
    uint2 hv = make_uint2(*reinterpret_cast<uint32_t*>(&h0), *reinterpret_cast<uint32_t*>(&h1));
    uint2 lv = make_uint2(*reinterpret_cast<uint32_t*>(&l0), *reinterpret_cast<uint32_t*>(&l1));
    reinterpret_cast<uint2*>(g_ahi + (size_t)v * 64)[lane] = hv;
    reinterpret_cast<uint2*>(g_alo + (size_t)v * 64)[lane] = lv;
}

// ================= persistent bf16 split-3 MMA GEMM (ldmatrix fragments) =========
__device__ __forceinline__ void mma_bf16(float* d, const uint32_t* a,
                                         uint32_t b0, uint32_t b1) {
    asm volatile(
        "mma.sync.aligned.m16n8k16.row.col.f32.bf16.bf16.f32 "
        "{%0,%1,%2,%3}, {%4,%5,%6,%7}, {%8,%9}, {%0,%1,%2,%3};"
        : "+f"(d[0]), "+f"(d[1]), "+f"(d[2]), "+f"(d[3])
        : "r"(a[0]), "r"(a[1]), "r"(a[2]), "r"(a[3]), "r"(b0), "r"(b1));
}
__device__ __forceinline__ void ldsm_x4(uint32_t* r, uint32_t addr) {
    asm volatile("ldmatrix.sync.aligned.m8n8.x4.shared.b16 {%0,%1,%2,%3}, [%4];"
                 : "=r"(r[0]), "=r"(r[1]), "=r"(r[2]), "=r"(r[3]) : "r"(addr));
}

// smem: Ahi(64x68) Alo(64x68) Whi(128x68) Wlo(128x68) u32 = 104448 B -> 2 CTA/SM
#define SMEM_MMA ((2 * 64 * PITCH + 2 * 128 * PITCH) * 4)
#define GEMM_GRID 296   // 2 CTA/SM * 148 SMs: persistent

template <bool LAYER1>
__global__ __launch_bounds__(512, 2)
void k_gemm_mma(const float* __restrict__ bias,
                const float* __restrict__ xres, float* __restrict__ outp, int n) {
    extern __shared__ uint32_t sm[];
    uint32_t* Ahi = sm;
    uint32_t* Alo = sm + 64 * PITCH;
    uint32_t* Whi = sm + 2 * 64 * PITCH;
    uint32_t* Wlo = Whi + 128 * PITCH;

    const uint32_t* whi = LAYER1 ? g_w1hi : g_w2hi;
    const uint32_t* wlo = LAYER1 ? g_w1lo : g_w2lo;

    const int tid = threadIdx.x;
    const int warp = tid >> 5;
    const int lane = tid & 31;
    const int g = lane >> 2;
    const int t = lane & 3;
    const int p = warp & 7;        // n-pair (16 cols)
    const int mh = warp >> 3;      // m-half (32 rows)
    float* out = LAYER1 ? g_h : outp;

    const int lr = lane & 15;
    const int lh = (lane >> 4) * 4;
    const uint32_t sAhi = (uint32_t)__cvta_generic_to_shared(Ahi);
    const uint32_t sAlo = (uint32_t)__cvta_generic_to_shared(Alo);
    const uint32_t sWhi = (uint32_t)__cvta_generic_to_shared(Whi);
    const uint32_t sWlo = (uint32_t)__cvta_generic_to_shared(Wlo);
    const uint32_t bRowOff = (uint32_t)((p * 16 + lr) * PITCH + lh) * 4u;

    // ---- W fill ONCE per persistent CTA: 128 rows x 16 uint4, hi+lo ----
#pragma unroll
    for (int it = 0; it < 4; it++) {
        int idx = tid + it * 512;            // 0..2047
        int r = idx >> 4, c = idx & 15;
        *reinterpret_cast<uint4*>(Whi + r * PITCH + c * 4) =
            reinterpret_cast<const uint4*>(whi + r * 64)[c];
        *reinterpret_cast<uint4*>(Wlo + r * PITCH + c * 4) =
            reinterpret_cast<const uint4*>(wlo + r * 64)[c];
    }

    const int nTiles = (n + 63) / 64;
    // ---- persistent loop over 64-row tiles ----
    for (int tileId = blockIdx.x; tileId < nTiles; tileId += GEMM_GRID) {
        const int rowBase = tileId * 64;

        // A fill: 64 rows x 16 uint4, hi+lo
#pragma unroll
        for (int it = 0; it < 2; it++) {
            int idx = tid + it * 512;        // 0..1023
            int r = idx >> 4, c = idx & 15;
            int grow = rowBase + r;
            uint4 vh = make_uint4(0u, 0u, 0u, 0u), vl = vh;
            if (grow < n) {
                vh = reinterpret_cast<const uint4*>(g_ahi + (size_t)grow * 64)[c];
                vl = reinterpret_cast<const uint4*>(g_alo + (size_t)grow * 64)[c];
            }
            *reinterpret_cast<uint4*>(Ahi + r * PITCH + c * 4) = vh;
            *reinterpret_cast<uint4*>(Alo + r * PITCH + c * 4) = vl;
        }
        __syncthreads();

        float acc[2][2][4];
#pragma unroll
        for (int mt = 0; mt < 2; mt++)
#pragma unroll
            for (int nt = 0; nt < 2; nt++)
#pragma unroll
                for (int q = 0; q < 4; q++) acc[mt][nt][q] = 0.f;

#pragma unroll
        for (int kt = 0; kt < 8; kt++) {
            const uint32_t kb4 = (uint32_t)(kt * 8) * 4u;
            uint32_t bh[4], bl[4];
            ldsm_x4(bh, sWhi + bRowOff + kb4);
            ldsm_x4(bl, sWlo + bRowOff + kb4);
#pragma unroll
            for (int mt = 0; mt < 2; mt++) {
                const uint32_t aOff =
                    (uint32_t)((mh * 32 + mt * 16 + lr) * PITCH + lh) * 4u + kb4;
                uint32_t ah[4], al[4];
                ldsm_x4(ah, sAhi + aOff);
                ldsm_x4(al, sAlo + aOff);
#pragma unroll
                for (int nt = 0; nt < 2; nt++) {
                    mma_bf16(acc[mt][nt], ah, bh[nt], bh[2 + nt]);   // hi*hi
                    mma_bf16(acc[mt][nt], al, bh[nt], bh[2 + nt]);   // lo*hi
                    mma_bf16(acc[mt][nt], ah, bl[nt], bl[2 + nt]);   // hi*lo
                }
            }
        }
        __syncthreads();   // A-tile fully consumed before next fill

        // epilogue for this tile
#pragma unroll
        for (int nt = 0; nt < 2; nt++) {
            int col = p * 16 + nt * 8 + 2 * t;
            float2 b2 = *reinterpret_cast<const float2*>(bias + col);
#pragma unroll
            for (int mt = 0; mt < 2; mt++) {
                int r0 = rowBase + mh * 32 + mt * 16 + g;
                int r1 = r0 + 8;
                if (r0 < n) {
                    float inv = g_degI[r0];
                    float o0 = (acc[mt][nt][0] + b2.x) * inv;
                    float o1 = (acc[mt][nt][1] + b2.y) * inv;
                    if (LAYER1) {
                        float2 x2 = *reinterpret_cast<const float2*>(xres + (size_t)r0 * D + col);
                        o0 = fmaxf(o0 + x2.x, 0.f);
                        o1 = fmaxf(o1 + x2.y, 0.f);
                    }
                    *reinterpret_cast<float2*>(out + (size_t)r0 * D + col) = make_float2(o0, o1);
                }
                if (r1 < n) {
                    float inv = g_degI[r1];
                    float o0 = (acc[mt][nt][2] + b2.x) * inv;
                    float o1 = (acc[mt][nt][3] + b2.y) * inv;
                    if (LAYER1) {
                        float2 x2 = *reinterpret_cast<const float2*>(xres + (size_t)r1 * D + col);
                        o0 = fmaxf(o0 + x2.x, 0.f);
                        o1 = fmaxf(o1 + x2.y, 0.f);
                    }
                    *reinterpret_cast<float2*>(out + (size_t)r1 * D + col) = make_float2(o0, o1);
                }
            }
        }
    }
}

// ---------------- launch ----------------
extern "C" void kernel_launch(void* const* d_in, const int* in_sizes, int n_in,
                              void* d_out, int out_size) {
    const float* x  = (const float*)d_in[0];
    const void*  ei = d_in[1];
    const float* W1 = (const float*)d_in[2];
    const float* b1 = (const float*)d_in[3];
    const float* W2 = (const float*)d_in[4];
    const float* b2 = (const float*)d_in[5];
    float* out      = (float*)d_out;

    const int n = in_sizes[0] / D;   // 100000
    const int E = in_sizes[1] / 2;   // 800000

    const int FB = (n + 255) / 256;
    const int NB = (n + 255) / 256;
    const int GAB = (n + 7) / 8;

    cudaFuncSetAttribute(k_gemm_mma<true>,  cudaFuncAttributeMaxDynamicSharedMemorySize, SMEM_MMA);
    cudaFuncSetAttribute(k_gemm_mma<false>, cudaFuncAttributeMaxDynamicSharedMemorySize, SMEM_MMA);

    // prep (4 launches)
    k_prep0<<<FB + 64, 256>>>(ei, n, FB, W1, W2);
    k_count<<<(2 * E / 4 + 255) / 256, 256>>>(ei, E);
    k_alloc<<<NB, 256>>>(n);
    k_bucket<<<(E / 2 + 255) / 256, 256>>>(ei, E);

    // layer 1: gather(x * degO) -> (ahi, alo); h = relu((agg@W1^T + b1)*invI + x)
    k_gather<false><<<GAB, 256>>>(x, n);
    k_gemm_mma<true><<<GEMM_GRID, 512, SMEM_MMA>>>(b1, x, nullptr, n);

    // layer 2: gather(h) -> (ahi, alo); out = (agg@W2^T + b2)*invI
    k_gather<true><<<GAB, 256>>>(nullptr, n);
    k_gemm_mma<false><<<GEMM_GRID, 512, SMEM_MMA>>>(b2, nullptr, out, n);
}